// round 11
// baseline (speedup 1.0000x reference)
#include <cuda_runtime.h>

// -------------------------------------------------------------------------
// out = Conv2(ReLU(Conv1( sum_t Ht[t,:,:] * upsample4(yt[b,t]) )))
//   yt:(32,32,64,64) Ht:(32,256,256) W1:(32,1,3,3) b1:(32) W2:(1,32,3,3) b2:(1)
//   out:(32,1,256,256) f32
// -------------------------------------------------------------------------

#define B_ 32
#define T_ 32
#define R_ 256

__device__ float g_x[B_ * R_ * R_];   // stage-1 scratch (8.4 MB static)

// ---------------- Stage 1: 4 pixels per thread, vectorized ----------------
__global__ void __launch_bounds__(256) stage1_kernel(
    const float* __restrict__ yt, const float* __restrict__ Ht)
{
    int tid  = threadIdx.x;
    int bx   = blockIdx.x;            // 0..63
    int t64  = tid & 63;
    int prow = tid >> 6;
    int p    = (bx << 2) + prow;
    int idx  = (p << 8) + (t64 << 2);
    int yoff = (bx << 6) + t64;

    int bbase = blockIdx.y << 3;
    float4 acc[8];
#pragma unroll
    for (int bo = 0; bo < 8; bo++) acc[bo] = make_float4(0.f, 0.f, 0.f, 0.f);

    const float* ytbase = yt + ((long)bbase << 17) + yoff;
#pragma unroll
    for (int t = 0; t < T_; t++) {
        float4 h4 = *(const float4*)(Ht + (t << 16) + idx);
        const float* ytp = ytbase + (t << 12);
#pragma unroll
        for (int bo = 0; bo < 8; bo++) {
            float yv = ytp[(long)bo << 17];
            acc[bo].x = fmaf(h4.x, yv, acc[bo].x);
            acc[bo].y = fmaf(h4.y, yv, acc[bo].y);
            acc[bo].z = fmaf(h4.z, yv, acc[bo].z);
            acc[bo].w = fmaf(h4.w, yv, acc[bo].w);
        }
    }
#pragma unroll
    for (int bo = 0; bo < 8; bo++)
        *(float4*)(g_x + ((long)(bbase + bo) << 16) + idx) = acc[bo];
}

// ---------------- Stage 2: warp-specialized fused conv ----------------
// Warps 0-3: conv1 producers (4 channels/group into double-buffered sh).
// Warps 4-7: conv2 consumers (2x4 output strips, all channels in-thread).
#define SHW 36
#define GBUF (4 * 34 * SHW)         // one group buffer: 4896 floats
#define SX_ELEMS (36 * 40)          // 1440 floats

__global__ void __launch_bounds__(256, 4) fused_conv_kernel(
    const float* __restrict__ W1, const float* __restrict__ b1,
    const float* __restrict__ W2, const float* __restrict__ b2,
    float* __restrict__ out)
{
    __shared__ __align__(16) float shb[2 * GBUF];   // 39168 B double buffer
    __shared__ __align__(16) float sx[SX_ELEMS];    //  5760 B
    __shared__ float sw1[288];
    __shared__ float sb1[32];
    __shared__ float sw2[288];

    int tid = threadIdx.x;
    int b   = blockIdx.y;
    int P0  = (blockIdx.x >> 3) << 5;
    int Q0  = (blockIdx.x & 7)  << 5;
    const float* xb = g_x + ((long)b << 16);

    // ---- stage weights + x tile (all 256 threads) ----
    for (int i = tid; i < 288; i += 256) { sw1[i] = W1[i]; sw2[i] = W2[i]; }
    if (tid < 32) sb1[tid] = b1[tid];
    for (int i = tid; i < SX_ELEMS; i += 256) {
        int r  = i / 40;
        int cc = i - r * 40;
        int gp = P0 - 2 + r;
        int gq = Q0 - 2 + cc;
        float v = 0.f;
        if (cc < 36 && (unsigned)gp < 256u && (unsigned)gq < 256u)
            v = xb[(gp << 8) + gq];
        sx[i] = v;
    }
    __syncthreads();

    bool is_c1 = (tid < 128);

    // --- producer mapping (tid 0..127): pair slot x (band, strip) ---
    int p2      = tid >> 6;              // 0..1 -> channels 2*p2, 2*p2+1 of group
    int spatial = tid & 63;              // 0..63; 63 idle
    int d       = spatial / 9;           // band 0..6 (5 rows each)
    int s       = spatial - d * 9;       // strip 0..8
    int col     = s << 2;
    int r0      = d * 5;
    bool c1act  = (spatial < 63);
    float cm0 = ((unsigned)(Q0 - 1 + col + 0) < 256u) ? 1.f : 0.f;
    float cm1 = ((unsigned)(Q0 - 1 + col + 1) < 256u) ? 1.f : 0.f;
    float cm2 = ((unsigned)(Q0 - 1 + col + 2) < 256u) ? 1.f : 0.f;
    float cm3 = ((unsigned)(Q0 - 1 + col + 3) < 256u) ? 1.f : 0.f;

    // --- consumer mapping (tid 128..255): 128 strips of 2x4 outputs ---
    int st = tid & 127;
    int oy = (st >> 3) << 1;             // 0,2,..,30
    int ox = (st & 7) << 2;              // 0,4,..,28
    float bb = *b2;
    float aA0 = bb, aA1 = bb, aA2 = bb, aA3 = bb;
    float aB0 = bb, aB1 = bb, aB2 = bb, aB3 = bb;

    for (int ph = 0; ph < 9; ph++) {
        if (is_c1) {
            // ===== conv1 + relu: produce group ph into shb[ph&1] =====
            if (ph < 8 && c1act) {
                int c0 = (ph << 2) + (p2 << 1);
                float w0[9], w1[9];
#pragma unroll
                for (int k = 0; k < 9; k++) { w0[k] = sw1[c0 * 9 + k]; w1[k] = sw1[c0 * 9 + 9 + k]; }
                float bi0 = sb1[c0], bi1 = sb1[c0 + 1];
                float* sh0 = shb + (ph & 1) * GBUF + (p2 << 1) * (34 * SHW);
                float* sh1 = sh0 + 34 * SHW;
                const float* xp = sx + r0 * 40 + col;

                float v[3][6];
#pragma unroll
                for (int j = 0; j < 2; j++) {
                    float4 q4 = *(const float4*)(xp + j * 40);
                    float2 q2 = *(const float2*)(xp + j * 40 + 4);
                    v[j][0] = q4.x; v[j][1] = q4.y; v[j][2] = q4.z;
                    v[j][3] = q4.w; v[j][4] = q2.x; v[j][5] = q2.y;
                }
#pragma unroll
                for (int i = 0; i < 5; i++) {
                    int row = r0 + i;
                    if (row < 34) {
                        float* vn = v[(i + 2) % 3];
                        {
                            float4 q4 = *(const float4*)(xp + (i + 2) * 40);
                            float2 q2 = *(const float2*)(xp + (i + 2) * 40 + 4);
                            vn[0] = q4.x; vn[1] = q4.y; vn[2] = q4.z;
                            vn[3] = q4.w; vn[4] = q2.x; vn[5] = q2.y;
                        }
                        const float* vr0 = v[i % 3];
                        const float* vr1 = v[(i + 1) % 3];
                        const float* vr2 = v[(i + 2) % 3];
                        float a0 = bi0, a1 = bi0, a2 = bi0, a3 = bi0;
                        float c0a = bi1, c1a = bi1, c2a = bi1, c3a = bi1;
#pragma unroll
                        for (int dx = 0; dx < 3; dx++) {
                            float wa0 = w0[dx], wa1 = w0[3 + dx], wa2 = w0[6 + dx];
                            float wb0 = w1[dx], wb1 = w1[3 + dx], wb2 = w1[6 + dx];
                            float x0 = vr0[dx + 0], x1 = vr0[dx + 1], x2 = vr0[dx + 2], x3 = vr0[dx + 3];
                            a0  = fmaf(wa0, x0, a0);  a1  = fmaf(wa0, x1, a1);
                            a2  = fmaf(wa0, x2, a2);  a3  = fmaf(wa0, x3, a3);
                            c0a = fmaf(wb0, x0, c0a); c1a = fmaf(wb0, x1, c1a);
                            c2a = fmaf(wb0, x2, c2a); c3a = fmaf(wb0, x3, c3a);
                            x0 = vr1[dx + 0]; x1 = vr1[dx + 1]; x2 = vr1[dx + 2]; x3 = vr1[dx + 3];
                            a0  = fmaf(wa1, x0, a0);  a1  = fmaf(wa1, x1, a1);
                            a2  = fmaf(wa1, x2, a2);  a3  = fmaf(wa1, x3, a3);
                            c0a = fmaf(wb1, x0, c0a); c1a = fmaf(wb1, x1, c1a);
                            c2a = fmaf(wb1, x2, c2a); c3a = fmaf(wb1, x3, c3a);
                            x0 = vr2[dx + 0]; x1 = vr2[dx + 1]; x2 = vr2[dx + 2]; x3 = vr2[dx + 3];
                            a0  = fmaf(wa2, x0, a0);  a1  = fmaf(wa2, x1, a1);
                            a2  = fmaf(wa2, x2, a2);  a3  = fmaf(wa2, x3, a3);
                            c0a = fmaf(wb2, x0, c0a); c1a = fmaf(wb2, x1, c1a);
                            c2a = fmaf(wb2, x2, c2a); c3a = fmaf(wb2, x3, c3a);
                        }
                        float mr = ((unsigned)(P0 - 1 + row) < 256u) ? 1.f : 0.f;
                        float m0 = mr * cm0, m1 = mr * cm1, m2 = mr * cm2, m3 = mr * cm3;
                        *(float4*)(sh0 + row * SHW + col) = make_float4(
                            fmaxf(a0, 0.f) * m0, fmaxf(a1, 0.f) * m1,
                            fmaxf(a2, 0.f) * m2, fmaxf(a3, 0.f) * m3);
                        *(float4*)(sh1 + row * SHW + col) = make_float4(
                            fmaxf(c0a, 0.f) * m0, fmaxf(c1a, 0.f) * m1,
                            fmaxf(c2a, 0.f) * m2, fmaxf(c3a, 0.f) * m3);
                    }
                }
            }
        } else {
            // ===== conv2: consume group ph-1 from shb[(ph-1)&1] =====
            if (ph >= 1) {
                int gprev = ph - 1;
                const float* buf = shb + (gprev & 1) * GBUF;
#pragma unroll
                for (int cw = 0; cw < 4; cw++) {
                    int c = (gprev << 2) + cw;
                    float w[9];
#pragma unroll
                    for (int k = 0; k < 9; k++) w[k] = sw2[c * 9 + k];
                    const float* hp = buf + cw * (34 * SHW) + oy * SHW + ox;

#pragma unroll
                    for (int j = 0; j < 4; j++) {
                        float4 q4 = *(const float4*)(hp + j * SHW);
                        float2 q2 = *(const float2*)(hp + j * SHW + 4);
                        float v0 = q4.x, v1 = q4.y, v2 = q4.z,
                              v3 = q4.w, v4 = q2.x, v5 = q2.y;
                        if (j < 3) {                       // out row 0, dy=j
                            float w0 = w[3 * j], w1 = w[3 * j + 1], w2 = w[3 * j + 2];
                            aA0 = fmaf(w0, v0, aA0); aA0 = fmaf(w1, v1, aA0); aA0 = fmaf(w2, v2, aA0);
                            aA1 = fmaf(w0, v1, aA1); aA1 = fmaf(w1, v2, aA1); aA1 = fmaf(w2, v3, aA1);
                            aA2 = fmaf(w0, v2, aA2); aA2 = fmaf(w1, v3, aA2); aA2 = fmaf(w2, v4, aA2);
                            aA3 = fmaf(w0, v3, aA3); aA3 = fmaf(w1, v4, aA3); aA3 = fmaf(w2, v5, aA3);
                        }
                        if (j >= 1) {                      // out row 1, dy=j-1
                            float w0 = w[3 * (j - 1)], w1 = w[3 * (j - 1) + 1], w2 = w[3 * (j - 1) + 2];
                            aB0 = fmaf(w0, v0, aB0); aB0 = fmaf(w1, v1, aB0); aB0 = fmaf(w2, v2, aB0);
                            aB1 = fmaf(w0, v1, aB1); aB1 = fmaf(w1, v2, aB1); aB1 = fmaf(w2, v3, aB1);
                            aB2 = fmaf(w0, v2, aB2); aB2 = fmaf(w1, v3, aB2); aB2 = fmaf(w2, v4, aB2);
                            aB3 = fmaf(w0, v3, aB3); aB3 = fmaf(w1, v4, aB3); aB3 = fmaf(w2, v5, aB3);
                        }
                    }
                }
            }
        }
        __syncthreads();   // phase boundary: buffer handoff
    }

    // ---- consumers write their 2x4 strips ----
    if (!is_c1) {
        float* ob = out + ((long)b << 16) + ((P0 + oy) << 8) + Q0 + ox;
        *(float4*)ob         = make_float4(aA0, aA1, aA2, aA3);
        *(float4*)(ob + 256) = make_float4(aB0, aB1, aB2, aB3);
    }
}

// -------------------------------------------------------------------------
extern "C" void kernel_launch(void* const* d_in, const int* in_sizes, int n_in,
                              void* d_out, int out_size)
{
    const float* yt = (const float*)d_in[0];
    const float* Ht = (const float*)d_in[1];
    const float* W1 = (const float*)d_in[2];
    const float* b1 = (const float*)d_in[3];
    const float* W2 = (const float*)d_in[4];
    const float* b2 = (const float*)d_in[5];
    float* out = (float*)d_out;

    stage1_kernel<<<dim3(64, 4), 256>>>(yt, Ht);
    fused_conv_kernel<<<dim3(64, 32), 256>>>(W1, b1, W2, b2, out);
}

// round 13
// speedup vs baseline: 1.0781x; 1.0781x over previous
#include <cuda_runtime.h>

// -------------------------------------------------------------------------
// out = Conv2(ReLU(Conv1( sum_t Ht[t,:,:] * upsample4(yt[b,t]) )))
//   yt:(32,32,64,64) Ht:(32,256,256) W1:(32,1,3,3) b1:(32) W2:(1,32,3,3) b2:(1)
//   out:(32,1,256,256) f32
// -------------------------------------------------------------------------

#define B_ 32
#define T_ 32
#define R_ 256

__device__ float g_x[B_ * R_ * R_];   // stage-1 scratch (8.4 MB static)

// ---------------- Stage 1: 4 pixels per thread, vectorized ----------------
__global__ void __launch_bounds__(256) stage1_kernel(
    const float* __restrict__ yt, const float* __restrict__ Ht)
{
    int tid  = threadIdx.x;
    int bx   = blockIdx.x;
    int t64  = tid & 63;
    int prow = tid >> 6;
    int p    = (bx << 2) + prow;
    int idx  = (p << 8) + (t64 << 2);
    int yoff = (bx << 6) + t64;

    int bbase = blockIdx.y << 3;
    float4 acc[8];
#pragma unroll
    for (int bo = 0; bo < 8; bo++) acc[bo] = make_float4(0.f, 0.f, 0.f, 0.f);

    const float* ytbase = yt + ((long)bbase << 17) + yoff;
#pragma unroll
    for (int t = 0; t < T_; t++) {
        float4 h4 = *(const float4*)(Ht + (t << 16) + idx);
        const float* ytp = ytbase + (t << 12);
#pragma unroll
        for (int bo = 0; bo < 8; bo++) {
            float yv = ytp[(long)bo << 17];
            acc[bo].x = fmaf(h4.x, yv, acc[bo].x);
            acc[bo].y = fmaf(h4.y, yv, acc[bo].y);
            acc[bo].z = fmaf(h4.z, yv, acc[bo].z);
            acc[bo].w = fmaf(h4.w, yv, acc[bo].w);
        }
    }
#pragma unroll
    for (int bo = 0; bo < 8; bo++)
        *(float4*)(g_x + ((long)(bbase + bo) << 16) + idx) = acc[bo];
}

// ---------------- Stage 2: fused conv1+relu+conv2 ----------------
#define SHW 36
#define SH_ELEMS (8 * 34 * SHW)     // 39168 B
#define SX_ELEMS (36 * 40)          //  5760 B

__global__ void __launch_bounds__(256, 3) fused_conv_kernel(
    const float* __restrict__ W1, const float* __restrict__ b1,
    const float* __restrict__ W2, const float* __restrict__ b2,
    float* __restrict__ out)
{
    __shared__ __align__(16) float sh[SH_ELEMS];
    __shared__ __align__(16) float sx[SX_ELEMS];
    __shared__ float sw1[288];
    __shared__ float sb1[32];
    __shared__ float sw2[288];

    int tid = threadIdx.x;
    int b   = blockIdx.y;
    int P0  = (blockIdx.x >> 3) << 5;
    int Q0  = (blockIdx.x & 7)  << 5;
    const float* xb = g_x + ((long)b << 16);

    // ---- stage weights + x tile ----
    for (int i = tid; i < 288; i += 256) { sw1[i] = W1[i]; sw2[i] = W2[i]; }
    if (tid < 32) sb1[tid] = b1[tid];
    for (int i = tid; i < SX_ELEMS; i += 256) {
        int r  = i / 40;
        int cc = i - r * 40;
        int gp = P0 - 2 + r;
        int gq = Q0 - 2 + cc;
        float v = 0.f;
        if (cc < 36 && (unsigned)gp < 256u && (unsigned)gq < 256u)
            v = xb[(gp << 8) + gq];
        sx[i] = v;
    }
    __syncthreads();

    // conv1 mapping: (channel-pair, band, strip) = 4 x 7 x 9 = 252 threads
    int p4   = tid / 63;
    int rem  = tid - p4 * 63;
    int d    = rem / 9;
    int s    = rem - d * 9;
    int col  = s << 2;
    int r0   = d * 5;
    bool act = (p4 < 4);
    float cm0 = ((unsigned)(Q0 - 1 + col + 0) < 256u) ? 1.f : 0.f;
    float cm1 = ((unsigned)(Q0 - 1 + col + 1) < 256u) ? 1.f : 0.f;
    float cm2 = ((unsigned)(Q0 - 1 + col + 2) < 256u) ? 1.f : 0.f;
    float cm3 = ((unsigned)(Q0 - 1 + col + 3) < 256u) ? 1.f : 0.f;

    // conv2 mapping: 64 strips (4 rows x 4 cols) x 4 channel-slots (2 ch each)
    int slot = tid >> 6;            // 0..3
    int strp = tid & 63;
    int oy = (strp >> 3) << 2;      // 0,4,..,28
    int ox = (strp & 7) << 2;       // 0,4,..,28
    float bb = *b2;
    float ac[4][4];                 // [out-row][out-col] partial sums
#pragma unroll
    for (int i = 0; i < 4; i++)
#pragma unroll
        for (int j = 0; j < 4; j++)
            ac[i][j] = (slot == 0) ? bb : 0.f;

    for (int g = 0; g < 4; g++) {
        // ===== conv1 + relu: marching rows, 2 channels per thread =====
        if (act) {
            int c0 = (g << 3) + (p4 << 1);
            float w0[9], w1[9];
#pragma unroll
            for (int k = 0; k < 9; k++) { w0[k] = sw1[c0 * 9 + k]; w1[k] = sw1[c0 * 9 + 9 + k]; }
            float bi0 = sb1[c0], bi1 = sb1[c0 + 1];
            float* sh0 = sh + (p4 << 1) * (34 * SHW);
            float* sh1 = sh0 + 34 * SHW;
            const float* xp = sx + r0 * 40 + col;

            float v[3][6];
#pragma unroll
            for (int j = 0; j < 2; j++) {
                float4 q4 = *(const float4*)(xp + j * 40);
                float2 q2 = *(const float2*)(xp + j * 40 + 4);
                v[j][0] = q4.x; v[j][1] = q4.y; v[j][2] = q4.z;
                v[j][3] = q4.w; v[j][4] = q2.x; v[j][5] = q2.y;
            }
#pragma unroll
            for (int i = 0; i < 5; i++) {
                int row = r0 + i;
                if (row < 34) {
                    float* vn = v[(i + 2) % 3];
                    {
                        float4 q4 = *(const float4*)(xp + (i + 2) * 40);
                        float2 q2 = *(const float2*)(xp + (i + 2) * 40 + 4);
                        vn[0] = q4.x; vn[1] = q4.y; vn[2] = q4.z;
                        vn[3] = q4.w; vn[4] = q2.x; vn[5] = q2.y;
                    }
                    const float* vr0 = v[i % 3];
                    const float* vr1 = v[(i + 1) % 3];
                    const float* vr2 = v[(i + 2) % 3];
                    float a0 = bi0, a1 = bi0, a2 = bi0, a3 = bi0;
                    float c0a = bi1, c1a = bi1, c2a = bi1, c3a = bi1;
#pragma unroll
                    for (int dx = 0; dx < 3; dx++) {
                        float wa0 = w0[dx], wa1 = w0[3 + dx], wa2 = w0[6 + dx];
                        float wb0 = w1[dx], wb1 = w1[3 + dx], wb2 = w1[6 + dx];
                        float x0 = vr0[dx + 0], x1 = vr0[dx + 1], x2 = vr0[dx + 2], x3 = vr0[dx + 3];
                        a0  = fmaf(wa0, x0, a0);  a1  = fmaf(wa0, x1, a1);
                        a2  = fmaf(wa0, x2, a2);  a3  = fmaf(wa0, x3, a3);
                        c0a = fmaf(wb0, x0, c0a); c1a = fmaf(wb0, x1, c1a);
                        c2a = fmaf(wb0, x2, c2a); c3a = fmaf(wb0, x3, c3a);
                        x0 = vr1[dx + 0]; x1 = vr1[dx + 1]; x2 = vr1[dx + 2]; x3 = vr1[dx + 3];
                        a0  = fmaf(wa1, x0, a0);  a1  = fmaf(wa1, x1, a1);
                        a2  = fmaf(wa1, x2, a2);  a3  = fmaf(wa1, x3, a3);
                        c0a = fmaf(wb1, x0, c0a); c1a = fmaf(wb1, x1, c1a);
                        c2a = fmaf(wb1, x2, c2a); c3a = fmaf(wb1, x3, c3a);
                        x0 = vr2[dx + 0]; x1 = vr2[dx + 1]; x2 = vr2[dx + 2]; x3 = vr2[dx + 3];
                        a0  = fmaf(wa2, x0, a0);  a1  = fmaf(wa2, x1, a1);
                        a2  = fmaf(wa2, x2, a2);  a3  = fmaf(wa2, x3, a3);
                        c0a = fmaf(wb2, x0, c0a); c1a = fmaf(wb2, x1, c1a);
                        c2a = fmaf(wb2, x2, c2a); c3a = fmaf(wb2, x3, c3a);
                    }
                    float mr = ((unsigned)(P0 - 1 + row) < 256u) ? 1.f : 0.f;
                    float m0 = mr * cm0, m1 = mr * cm1, m2 = mr * cm2, m3 = mr * cm3;
                    *(float4*)(sh0 + row * SHW + col) = make_float4(
                        fmaxf(a0, 0.f) * m0, fmaxf(a1, 0.f) * m1,
                        fmaxf(a2, 0.f) * m2, fmaxf(a3, 0.f) * m3);
                    *(float4*)(sh1 + row * SHW + col) = make_float4(
                        fmaxf(c0a, 0.f) * m0, fmaxf(c1a, 0.f) * m1,
                        fmaxf(c2a, 0.f) * m2, fmaxf(c3a, 0.f) * m3);
                }
            }
        }
        __syncthreads();

        // ===== conv2: 4x4 outputs, 2 channels per slot, rolling rows =====
        {
#pragma unroll
            for (int cc = 0; cc < 2; cc++) {
                int c8v = (slot << 1) + cc;
                int c   = (g << 3) + c8v;
                float w[9];
#pragma unroll
                for (int k = 0; k < 9; k++) w[k] = sw2[c * 9 + k];
                const float* hp = sh + c8v * (34 * SHW) + oy * SHW + ox;

#pragma unroll
                for (int j = 0; j < 6; j++) {
                    float4 q4 = *(const float4*)(hp + j * SHW);
                    float2 q2 = *(const float2*)(hp + j * SHW + 4);
                    float v0 = q4.x, v1 = q4.y, v2 = q4.z,
                          v3 = q4.w, v4 = q2.x, v5 = q2.y;
                    // sh row oy+j feeds out rows rt = j-2..j (dy = j-rt)
#pragma unroll
                    for (int rt = 0; rt < 4; rt++) {
                        if (rt <= j && j - rt <= 2) {
                            int dy = j - rt;
                            float w0 = w[3 * dy], w1 = w[3 * dy + 1], w2 = w[3 * dy + 2];
                            ac[rt][0] = fmaf(w0, v0, ac[rt][0]);
                            ac[rt][0] = fmaf(w1, v1, ac[rt][0]);
                            ac[rt][0] = fmaf(w2, v2, ac[rt][0]);
                            ac[rt][1] = fmaf(w0, v1, ac[rt][1]);
                            ac[rt][1] = fmaf(w1, v2, ac[rt][1]);
                            ac[rt][1] = fmaf(w2, v3, ac[rt][1]);
                            ac[rt][2] = fmaf(w0, v2, ac[rt][2]);
                            ac[rt][2] = fmaf(w1, v3, ac[rt][2]);
                            ac[rt][2] = fmaf(w2, v4, ac[rt][2]);
                            ac[rt][3] = fmaf(w0, v3, ac[rt][3]);
                            ac[rt][3] = fmaf(w1, v4, ac[rt][3]);
                            ac[rt][3] = fmaf(w2, v5, ac[rt][3]);
                        }
                    }
                }
            }
        }
        __syncthreads();   // before next group's conv1 overwrites sh
    }

    // ---- combine 4 channel-slots via smem (sh free now) ----
    if (slot != 0) {
        float* rp = sh + ((slot - 1) * 64 + strp) * 16;
#pragma unroll
        for (int i = 0; i < 4; i++)
#pragma unroll
            for (int j = 0; j < 4; j++)
                rp[i * 4 + j] = ac[i][j];
    }
    __syncthreads();
    if (slot == 0) {
#pragma unroll
        for (int sl = 0; sl < 3; sl++) {
            const float* rp = sh + (sl * 64 + strp) * 16;
#pragma unroll
            for (int i = 0; i < 4; i++)
#pragma unroll
                for (int j = 0; j < 4; j++)
                    ac[i][j] += rp[i * 4 + j];
        }
        float* ob = out + ((long)b << 16) + ((P0 + oy) << 8) + Q0 + ox;
#pragma unroll
        for (int i = 0; i < 4; i++)
            *(float4*)(ob + (i << 8)) = make_float4(ac[i][0], ac[i][1], ac[i][2], ac[i][3]);
    }
}

// -------------------------------------------------------------------------
extern "C" void kernel_launch(void* const* d_in, const int* in_sizes, int n_in,
                              void* d_out, int out_size)
{
    const float* yt = (const float*)d_in[0];
    const float* Ht = (const float*)d_in[1];
    const float* W1 = (const float*)d_in[2];
    const float* b1 = (const float*)d_in[3];
    const float* W2 = (const float*)d_in[4];
    const float* b2 = (const float*)d_in[5];
    float* out = (float*)d_out;

    stage1_kernel<<<dim3(64, 4), 256>>>(yt, Ht);
    fused_conv_kernel<<<dim3(64, 32), 256>>>(W1, b1, W2, b2, out);
}